// round 1
// baseline (speedup 1.0000x reference)
#include <cuda_runtime.h>

// Blur: depthwise 4x4 FIR (separable [1,3,3,1] outer [1,3,3,1] / 16), pad (1,1).
// Input  (4,128,513,513) f32, Output (4,128,512,512) f32.
//
// out[y][x] = (1/16) * sum_{i,j} k_i k_j * in[y+i-1][x+j-1],  k = [1,3,3,1]
// Factored: h(r)[x] = sum_j k_j in[r][x+j-1]  (horizontal pass, registers)
//           out[y]  = (h(y-1)+h(y+2)) + 3*(h(y)+h(y+1)), scaled by 1/16.
//
// One block = one full-width row strip of one (n,c) plane.
// 256 threads * 2 output cols = 512 cols. Rolling 4-entry ring of horizontal
// sums -> each input row is loaded exactly once per strip (plus 3-row halo).

#define W_IN   513
#define H_IN   513
#define W_OUT  512
#define H_OUT  512
#define STRIP  64
#define NPLANE 512   // 4*128

__global__ __launch_bounds__(256, 6)
void blur_sep_kernel(const float* __restrict__ in, float* __restrict__ out)
{
    const int tid   = threadIdx.x;        // 0..255
    const int x0    = tid << 1;           // output cols x0, x0+1
    const int plane = blockIdx.y;
    const int y0    = blockIdx.x * STRIP;

    const float* ip = in  + (size_t)plane * (W_IN  * H_IN);
    float*       op = out + (size_t)plane * (W_OUT * H_OUT);

    const bool lv = (x0 >= 1);            // col x0-1 valid (tid > 0)
    const bool rv = (x0 + 3 < W_IN);      // col x0+3 valid (tid < 255)

    // Horizontal FIR for one input row r -> float2 of partial sums for 2 cols.
    auto hrow = [&](int r) -> float2 {
        float2 res;
        if ((unsigned)r < (unsigned)H_IN) {
            const float* __restrict__ row = ip + (size_t)r * W_IN;
            float v0 = lv ? __ldg(row + x0 - 1) : 0.0f;
            float v1 = __ldg(row + x0);
            float v2 = __ldg(row + x0 + 1);
            float v3 = __ldg(row + x0 + 2);
            float v4 = rv ? __ldg(row + x0 + 3) : 0.0f;
            res.x = (v0 + v3) + 3.0f * (v1 + v2);
            res.y = (v1 + v4) + 3.0f * (v2 + v3);
        } else {
            res.x = 0.0f; res.y = 0.0f;   // zero padding rows (-1, 513, 514)
        }
        return res;
    };

    float2 h[4];
    h[0] = hrow(y0 - 1);
    h[1] = hrow(y0);
    h[2] = hrow(y0 + 1);

    #pragma unroll 4
    for (int i = 0; i < STRIP; ++i) {
        const int y = y0 + i;
        float2 hd = hrow(y + 2);
        h[(i + 3) & 3] = hd;
        float2 ha = h[ i      & 3];
        float2 hb = h[(i + 1) & 3];
        float2 hc = h[(i + 2) & 3];

        float2 o;
        o.x = ((ha.x + hd.x) + 3.0f * (hb.x + hc.x)) * 0.0625f;
        o.y = ((ha.y + hd.y) + 3.0f * (hb.y + hc.y)) * 0.0625f;

        *reinterpret_cast<float2*>(op + (size_t)y * W_OUT + x0) = o;
    }
}

extern "C" void kernel_launch(void* const* d_in, const int* in_sizes, int n_in,
                              void* d_out, int out_size)
{
    const float* in  = (const float*)d_in[0];
    float*       out = (float*)d_out;
    // d_in[1] is the 4x4 FIR buffer; its values are the fixed normalized
    // [1,3,3,1] outer product * factor^2, folded into the constants above.

    dim3 grid(H_OUT / STRIP, NPLANE);   // (8, 512)
    blur_sep_kernel<<<grid, 256>>>(in, out);
}

// round 2
// speedup vs baseline: 1.2673x; 1.2673x over previous
#include <cuda_runtime.h>

// Blur: depthwise 4x4 FIR (separable [1,3,3,1] ⊗ [1,3,3,1] / 16), pad (1,1).
// Input (4,128,513,513) f32 -> Output (4,128,512,512) f32.
//
// Round-2 structure: each warp owns a 128-col output strip. Per input row it
// stages its 131-float window into warp-private smem with 5 unit-stride
// coalesced LDGs (dense DRAM requests, ~1 load/output), then computes the
// horizontal FIR from two aligned LDS.128 per thread (4 cols/thread).
// Vertical FIR: rolling 4-row register ring. Output: one STG.128/thread/row.
// Warp-private double-buffered smem, one __syncwarp per row.

#define W_IN   513
#define H_IN   513
#define W_OUT  512
#define H_OUT  512
#define STRIP  64
#define BUFSZ  160      // 131 needed; padded so all 5 stores are unconditional
#define NPLANE 512      // 4*128

__global__ __launch_bounds__(128, 10)
void blur_smem_kernel(const float* __restrict__ in, float* __restrict__ out)
{
    __shared__ float sbuf[4][2][BUFSZ];   // [warp][double-buffer][idx]

    const int tid   = threadIdx.x;
    const int warp  = tid >> 5;
    const int lane  = tid & 31;
    const int plane = blockIdx.y;
    const int y0    = blockIdx.x * STRIP;
    const int wx0   = warp << 7;          // warp's first output col: 0/128/256/384

    const float* ip = in  + (size_t)plane * (W_IN  * H_IN);
    float*       op = out + (size_t)plane * (W_OUT * H_OUT);

    // Staging plan: buf[i] = in[row][wx0 - 1 + i] for i in [0,131), zero-padded.
    // Lane stores idx = lane + 32k, k = 0..4. Branchless: clamped column
    // address * {0,1} mask (reads stay in-bounds, zeros where logical pad).
    int   gc[5];
    float mk[5];
    #pragma unroll
    for (int k = 0; k < 5; ++k) {
        int  idx = lane + 32 * k;
        int  g   = wx0 - 1 + idx;
        bool ok  = (idx < 131) && (g >= 0) && (g < W_IN);
        gc[k] = min(max(g, 0), W_IN - 1);
        mk[k] = ok ? 1.0f : 0.0f;
    }

    float* __restrict__ buf0 = &sbuf[warp][0][0];
    float* __restrict__ buf1 = &sbuf[warp][1][0];

    // Stage one input row (row index r, zero rows map to mask 0, address clamped).
    auto stage = [&](int r, float* __restrict__ buf) {
        const float* __restrict__ rp = ip + (size_t)max(0, min(r, H_IN - 1)) * W_IN;
        float rm = ((unsigned)r < (unsigned)H_IN) ? 1.0f : 0.0f;
        #pragma unroll
        for (int k = 0; k < 5; ++k)
            buf[lane + 32 * k] = rm * mk[k] * __ldg(rp + gc[k]);
    };

    // Horizontal FIR from staged row: this thread's window is buf[4l .. 4l+7]
    // = in[x0-1 .. x0+6] with x0 = wx0 + 4*lane. Two aligned LDS.128, no conflicts.
    auto hcalc = [&](const float* __restrict__ buf) -> float4 {
        float4 a = *reinterpret_cast<const float4*>(buf + 4 * lane);       // x0-1..x0+2
        float4 c = *reinterpret_cast<const float4*>(buf + 4 * lane + 4);   // x0+3..x0+6
        float4 h;
        h.x = a.x + 3.0f * (a.y + a.z) + a.w;
        h.y = a.y + 3.0f * (a.z + a.w) + c.x;
        h.z = a.z + 3.0f * (a.w + c.x) + c.y;
        h.w = a.w + 3.0f * (c.x + c.y) + c.z;
        return h;
    };

    float4 h[4];
    stage(y0 - 1, buf0); __syncwarp(); h[0] = hcalc(buf0);
    stage(y0,     buf1); __syncwarp(); h[1] = hcalc(buf1);
    stage(y0 + 1, buf0); __syncwarp(); h[2] = hcalc(buf0);

    #pragma unroll 4
    for (int i = 0; i < STRIP; ++i) {
        float* __restrict__ buf = (i & 1) ? buf0 : buf1;
        stage(y0 + 2 + i, buf);
        __syncwarp();
        float4 hd = hcalc(buf);
        h[(i + 3) & 3] = hd;
        float4 ha = h[ i      & 3];
        float4 hb = h[(i + 1) & 3];
        float4 hc = h[(i + 2) & 3];

        float4 o;
        o.x = (ha.x + hd.x + 3.0f * (hb.x + hc.x)) * 0.0625f;
        o.y = (ha.y + hd.y + 3.0f * (hb.y + hc.y)) * 0.0625f;
        o.z = (ha.z + hd.z + 3.0f * (hb.z + hc.z)) * 0.0625f;
        o.w = (ha.w + hd.w + 3.0f * (hb.w + hc.w)) * 0.0625f;

        *reinterpret_cast<float4*>(op + (size_t)(y0 + i) * W_OUT + wx0 + 4 * lane) = o;
    }
}

extern "C" void kernel_launch(void* const* d_in, const int* in_sizes, int n_in,
                              void* d_out, int out_size)
{
    const float* in  = (const float*)d_in[0];
    float*       out = (float*)d_out;
    // d_in[1] is the 4x4 FIR buffer: fixed normalized [1,3,3,1] outer product
    // * factor^2 == ([1,3,3,1] ⊗ [1,3,3,1]) / 16, folded into the constants.

    dim3 grid(H_OUT / STRIP, NPLANE);   // (8, 512)
    blur_smem_kernel<<<grid, 128>>>(in, out);
}